// round 17
// baseline (speedup 1.0000x reference)
#include <cuda_runtime.h>
#include <cuda_fp16.h>
#include <cstdint>

// Problem constants
#define BATCH   16384
#define MAXF    32
#define NFEAT   768
#define FT_OUT  1024
#define FULL_MASK 0xFFFFFFFFu
#define ROW_BYTES (FT_OUT * 2)     // 2048 B per fp16 row

// fp16 copies, rebuilt every kernel_launch (deterministic).
__device__ __half g_ftw_h[NFEAT * FT_OUT];   // table
__device__ __half g_ftb_h[FT_OUT];           // bias
__device__ __half g_ow_h [2 * FT_OUT];       // output weights

// ---------------------------------------------------------------------------
// Kernel 1: convert table + bias + out_w fp32 -> fp16.
// Blocks 0..95: table, 8 float4 per thread (independent loads -> DRAM MLP).
// Block 96: ftb + ow.
// ---------------------------------------------------------------------------
__global__ void convert_kernel(const float* __restrict__ ftw,
                               const float* __restrict__ ftb,
                               const float* __restrict__ ow) {
    const int bid = blockIdx.x;
    if (bid < 96) {
        const float4* src = reinterpret_cast<const float4*>(ftw);
        __half2* dst = reinterpret_cast<__half2*>(g_ftw_h);
        const int base = bid * (256 * 8) + threadIdx.x;
        float4 v[8];
        #pragma unroll
        for (int j = 0; j < 8; ++j) v[j] = src[base + j * 256];
        #pragma unroll
        for (int j = 0; j < 8; ++j) {
            const int i = base + j * 256;
            dst[2 * i + 0] = __floats2half2_rn(v[j].x, v[j].y);
            dst[2 * i + 1] = __floats2half2_rn(v[j].z, v[j].w);
        }
    } else {
        const int t = threadIdx.x;
        for (int j = t; j < FT_OUT / 2; j += 256) {
            float2 x = reinterpret_cast<const float2*>(ftb)[j];
            reinterpret_cast<__half2*>(g_ftb_h)[j] = __floats2half2_rn(x.x, x.y);
        }
        for (int j = t; j < FT_OUT; j += 256) {
            float2 x = reinterpret_cast<const float2*>(ow)[j];
            reinterpret_cast<__half2*>(g_ow_h)[j] = __floats2half2_rn(x.x, x.y);
        }
    }
}

// ---------------------------------------------------------------------------
// Kernel 2: TWO warps per sample (512 cols each), 4 samples per CTA.
// Staging precomputes byte offsets + half2 values. Inner iteration: 2 features,
// all 8 LDG.128 issued before FMAs (MLP=8), plus L1 prefetch of iteration
// c+3's 4 rows (one 128B line per lane). fp16 epilogue tables.
// ---------------------------------------------------------------------------
__global__ void __launch_bounds__(256, 4)
nnue_main_kernel(const float* __restrict__ values,
                 const int*   __restrict__ stm_idx,
                 const int*   __restrict__ nstm_idx,
                 const float* __restrict__ out_b,
                 float*       __restrict__ out)
{
    __shared__ uint2    s_off[4][MAXF];   // {offS_bytes, offN_bytes}
    __shared__ unsigned s_vh [4][MAXF];   // half2(value) bits
    __shared__ float    s_partial[8];

    const int tid       = threadIdx.x;
    const int warpInCta = tid >> 5;
    const int lane      = tid & 31;
    const int sInCta    = warpInCta >> 1;     // 4 samples per CTA
    const int h         = warpInCta & 1;      // column half: 0 or 1
    const int b         = blockIdx.x * 4 + sInCta;

    // Stage metadata: threads 0..127, one (sample, feature) each
    if (tid < 128) {
        const int s = tid >> 5;
        const int f = tid & 31;
        const int bg = blockIdx.x * 4 + s;
        const unsigned is = (unsigned)stm_idx [bg * MAXF + f];
        const unsigned in = (unsigned)nstm_idx[bg * MAXF + f];
        const float    v  = values [bg * MAXF + f];
        s_off[s][f] = make_uint2(is * ROW_BYTES, in * ROW_BYTES);
        __half2 vh = __float2half2_rn(v);
        s_vh[s][f] = *reinterpret_cast<unsigned*>(&vh);
    }
    __syncthreads();

    // Warp owns cols [h*512, h*512+512) = bytes [h*1024, h*1024+1024) of a row.
    const char* Wq = reinterpret_cast<const char*>(g_ftw_h) + h * 1024 + lane * 16;
    // Prefetch base: lane covers line (lane&7) of row (lane>>3) in the warp span.
    const char* Wp = reinterpret_cast<const char*>(g_ftw_h) + h * 1024 + (lane & 7) * 128;
    const uint4* off4 = reinterpret_cast<const uint4*>(s_off[sInCta]); // 2 feats
    const uint2* vh2  = reinterpret_cast<const uint2*>(s_vh[sInCta]);  // 2 feats
    const unsigned* offw = reinterpret_cast<const unsigned*>(s_off[sInCta]);
    const int prow = lane >> 3;   // which of the 4 row-offsets this lane prefetches

    __half2 accS[8], accN[8];
    #pragma unroll
    for (int i = 0; i < 8; ++i) {
        accS[i] = __half2half2(__float2half_rn(0.0f));
        accN[i] = accS[i];
    }

    // Warm the pipeline: prefetch iterations 0..2
    #pragma unroll
    for (int c = 0; c < 3; ++c) {
        unsigned opf = offw[c * 4 + prow];
        asm volatile("prefetch.global.L1 [%0];" :: "l"(Wp + opf));
    }

    #pragma unroll 4
    for (int c = 0; c < 16; ++c) {              // 2 features per iteration
        const uint4 o  = off4[c];               // {offS0, offN0, offS1, offN1}
        uint2 vv = vh2[c];
        const __half2 v0 = *reinterpret_cast<__half2*>(&vv.x);
        const __half2 v1 = *reinterpret_cast<__half2*>(&vv.y);

        const char* rS0 = Wq + o.x;
        const char* rN0 = Wq + o.y;
        const char* rS1 = Wq + o.z;
        const char* rN1 = Wq + o.w;

        // Issue all 8 independent LDG.128 first (MLP = 8)
        uint4 s0a = *reinterpret_cast<const uint4*>(rS0);
        uint4 s0b = *reinterpret_cast<const uint4*>(rS0 + 512);
        uint4 n0a = *reinterpret_cast<const uint4*>(rN0);
        uint4 n0b = *reinterpret_cast<const uint4*>(rN0 + 512);
        uint4 s1a = *reinterpret_cast<const uint4*>(rS1);
        uint4 s1b = *reinterpret_cast<const uint4*>(rS1 + 512);
        uint4 n1a = *reinterpret_cast<const uint4*>(rN1);
        uint4 n1b = *reinterpret_cast<const uint4*>(rN1 + 512);

        // Prefetch iteration c+3's rows (one line per lane)
        if (c < 13) {
            unsigned opf = offw[(c + 3) * 4 + prow];
            asm volatile("prefetch.global.L1 [%0];" :: "l"(Wp + opf));
        }

        accS[0] = __hfma2(v0, *reinterpret_cast<__half2*>(&s0a.x), accS[0]);
        accS[1] = __hfma2(v0, *reinterpret_cast<__half2*>(&s0a.y), accS[1]);
        accS[2] = __hfma2(v0, *reinterpret_cast<__half2*>(&s0a.z), accS[2]);
        accS[3] = __hfma2(v0, *reinterpret_cast<__half2*>(&s0a.w), accS[3]);
        accS[4] = __hfma2(v0, *reinterpret_cast<__half2*>(&s0b.x), accS[4]);
        accS[5] = __hfma2(v0, *reinterpret_cast<__half2*>(&s0b.y), accS[5]);
        accS[6] = __hfma2(v0, *reinterpret_cast<__half2*>(&s0b.z), accS[6]);
        accS[7] = __hfma2(v0, *reinterpret_cast<__half2*>(&s0b.w), accS[7]);
        accN[0] = __hfma2(v0, *reinterpret_cast<__half2*>(&n0a.x), accN[0]);
        accN[1] = __hfma2(v0, *reinterpret_cast<__half2*>(&n0a.y), accN[1]);
        accN[2] = __hfma2(v0, *reinterpret_cast<__half2*>(&n0a.z), accN[2]);
        accN[3] = __hfma2(v0, *reinterpret_cast<__half2*>(&n0a.w), accN[3]);
        accN[4] = __hfma2(v0, *reinterpret_cast<__half2*>(&n0b.x), accN[4]);
        accN[5] = __hfma2(v0, *reinterpret_cast<__half2*>(&n0b.y), accN[5]);
        accN[6] = __hfma2(v0, *reinterpret_cast<__half2*>(&n0b.z), accN[6]);
        accN[7] = __hfma2(v0, *reinterpret_cast<__half2*>(&n0b.w), accN[7]);

        accS[0] = __hfma2(v1, *reinterpret_cast<__half2*>(&s1a.x), accS[0]);
        accS[1] = __hfma2(v1, *reinterpret_cast<__half2*>(&s1a.y), accS[1]);
        accS[2] = __hfma2(v1, *reinterpret_cast<__half2*>(&s1a.z), accS[2]);
        accS[3] = __hfma2(v1, *reinterpret_cast<__half2*>(&s1a.w), accS[3]);
        accS[4] = __hfma2(v1, *reinterpret_cast<__half2*>(&s1b.x), accS[4]);
        accS[5] = __hfma2(v1, *reinterpret_cast<__half2*>(&s1b.y), accS[5]);
        accS[6] = __hfma2(v1, *reinterpret_cast<__half2*>(&s1b.z), accS[6]);
        accS[7] = __hfma2(v1, *reinterpret_cast<__half2*>(&s1b.w), accS[7]);
        accN[0] = __hfma2(v1, *reinterpret_cast<__half2*>(&n1a.x), accN[0]);
        accN[1] = __hfma2(v1, *reinterpret_cast<__half2*>(&n1a.y), accN[1]);
        accN[2] = __hfma2(v1, *reinterpret_cast<__half2*>(&n1a.z), accN[2]);
        accN[3] = __hfma2(v1, *reinterpret_cast<__half2*>(&n1a.w), accN[3]);
        accN[4] = __hfma2(v1, *reinterpret_cast<__half2*>(&n1b.x), accN[4]);
        accN[5] = __hfma2(v1, *reinterpret_cast<__half2*>(&n1b.y), accN[5]);
        accN[6] = __hfma2(v1, *reinterpret_cast<__half2*>(&n1b.z), accN[6]);
        accN[7] = __hfma2(v1, *reinterpret_cast<__half2*>(&n1b.w), accN[7]);
    }

    // ----- epilogue: fp32 bias add, clip [0,1], dot with out_w (fp16 tables) -----
    float partial = 0.0f;
    #pragma unroll
    for (int u = 0; u < 2; ++u) {
        const int colbase = h * 512 + u * 256 + lane * 8;
        uint4 bbh = *reinterpret_cast<const uint4*>(g_ftb_h + colbase);
        float2 bb0 = __half22float2(*reinterpret_cast<__half2*>(&bbh.x));
        float2 bb1 = __half22float2(*reinterpret_cast<__half2*>(&bbh.y));
        float2 bb2 = __half22float2(*reinterpret_cast<__half2*>(&bbh.z));
        float2 bb3 = __half22float2(*reinterpret_cast<__half2*>(&bbh.w));

        #pragma unroll
        for (int side = 0; side < 2; ++side) {
            const __half2* acc = (side == 0) ? &accS[u*4] : &accN[u*4];
            uint4 wwh = *reinterpret_cast<const uint4*>(g_ow_h + side * FT_OUT + colbase);
            float2 w0 = __half22float2(*reinterpret_cast<__half2*>(&wwh.x));
            float2 w1 = __half22float2(*reinterpret_cast<__half2*>(&wwh.y));
            float2 w2 = __half22float2(*reinterpret_cast<__half2*>(&wwh.z));
            float2 w3 = __half22float2(*reinterpret_cast<__half2*>(&wwh.w));
            float2 p0 = __half22float2(acc[0]);
            float2 p1 = __half22float2(acc[1]);
            float2 p2 = __half22float2(acc[2]);
            float2 p3 = __half22float2(acc[3]);
            float hh;
            hh = fminf(fmaxf(p0.x + bb0.x, 0.f), 1.f); partial = fmaf(hh, w0.x, partial);
            hh = fminf(fmaxf(p0.y + bb0.y, 0.f), 1.f); partial = fmaf(hh, w0.y, partial);
            hh = fminf(fmaxf(p1.x + bb1.x, 0.f), 1.f); partial = fmaf(hh, w1.x, partial);
            hh = fminf(fmaxf(p1.y + bb1.y, 0.f), 1.f); partial = fmaf(hh, w1.y, partial);
            hh = fminf(fmaxf(p2.x + bb2.x, 0.f), 1.f); partial = fmaf(hh, w2.x, partial);
            hh = fminf(fmaxf(p2.y + bb2.y, 0.f), 1.f); partial = fmaf(hh, w2.y, partial);
            hh = fminf(fmaxf(p3.x + bb3.x, 0.f), 1.f); partial = fmaf(hh, w3.x, partial);
            hh = fminf(fmaxf(p3.y + bb3.y, 0.f), 1.f); partial = fmaf(hh, w3.y, partial);
        }
    }

    // warp reduce
    #pragma unroll
    for (int off = 16; off > 0; off >>= 1)
        partial += __shfl_xor_sync(FULL_MASK, partial, off);

    if (lane == 0) s_partial[warpInCta] = partial;
    __syncthreads();

    // half-0 warp of each sample finalizes
    if (h == 0 && lane == 0) {
        float x = s_partial[warpInCta] + s_partial[warpInCta + 1] + out_b[0];
        out[b] = 1.0f / (1.0f + __expf(-x));
    }
}

// ---------------------------------------------------------------------------
// kernel_launch
// Inputs: values, stm_indices, nstm_indices, ft_w, ft_b, out_w, out_b
// ---------------------------------------------------------------------------
extern "C" void kernel_launch(void* const* d_in, const int* in_sizes, int n_in,
                              void* d_out, int out_size)
{
    const float* values   = (const float*)d_in[0];
    const int*   stm_idx  = (const int*)  d_in[1];
    const int*   nstm_idx = (const int*)  d_in[2];
    const float* ft_w     = (const float*)d_in[3];
    const float* ft_b     = (const float*)d_in[4];
    const float* out_w    = (const float*)d_in[5];
    const float* out_b    = (const float*)d_in[6];
    float*       out      = (float*)d_out;

    convert_kernel<<<97, 256>>>(ft_w, ft_b, out_w);
    // 4 samples per CTA -> 4096 CTAs
    nnue_main_kernel<<<BATCH / 4, 256>>>(values, stm_idx, nstm_idx, out_b, out);
}